// round 2
// baseline (speedup 1.0000x reference)
#include <cuda_runtime.h>

#define NPTS 500000
#define NCLS 20
#define NK   16

// Scratch: probs table (40 MB, fits 126MB L2) + accumulators. Device globals (no alloc).
__device__ float g_probs[(size_t)NPTS * NCLS];
__device__ float g_acc[2];   // [0]=sum of mean_dist over valid pts, [1]=valid count

__global__ void zero_acc_kernel() {
    g_acc[0] = 0.0f;
    g_acc[1] = 0.0f;
}

// One thread per row: 20-class softmax, vectorized float4 (rows are 80B = 16B-aligned).
__global__ void softmax_kernel(const float* __restrict__ logits) {
    int n = blockIdx.x * blockDim.x + threadIdx.x;
    if (n >= NPTS) return;
    const float4* src = reinterpret_cast<const float4*>(logits + (size_t)n * NCLS);
    float4 v[5];
#pragma unroll
    for (int i = 0; i < 5; i++) v[i] = src[i];
    float* f = reinterpret_cast<float*>(v);
    float m = f[0];
#pragma unroll
    for (int i = 1; i < NCLS; i++) m = fmaxf(m, f[i]);
    float s = 0.0f;
#pragma unroll
    for (int i = 0; i < NCLS; i++) { f[i] = __expf(f[i] - m); s += f[i]; }
    float inv = 1.0f / s;
#pragma unroll
    for (int i = 0; i < NCLS; i++) f[i] *= inv;
    float4* dst = reinterpret_cast<float4*>(g_probs + (size_t)n * NCLS);
#pragma unroll
    for (int i = 0; i < 5; i++) dst[i] = v[i];
}

// Warp-per-point gather + distance.
// Lane layout: grp = lane>>4 (0/1), pair = lane&15. Lanes with pair<10 own class
// pair {2*pair, 2*pair+1} as a float2. In step s, group 0 processes neighbor 2s,
// group 1 processes neighbor 2s+1 -> one LDG.64 covers two neighbor rows.
__global__ void loss_kernel(const int* __restrict__ nbr,
                            const int* __restrict__ labels) {
    const int lane = threadIdx.x & 31;
    const int warpInBlock = threadIdx.x >> 5;
    const int warpsPerBlock = blockDim.x >> 5;
    const int gwarp = blockIdx.x * warpsPerBlock + warpInBlock;
    const int totalWarps = gridDim.x * warpsPerBlock;
    const int grp  = lane >> 4;
    const int pair = lane & 15;
    const bool active = (pair < 10);

    float warpSum = 0.0f;
    float warpCnt = 0.0f;

    for (int n = gwarp; n < NPTS; n += totalWarps) {
        int lab = labels[n];                    // same addr all lanes -> broadcast
        bool pvalid = (lab != -1);

        // Each of lanes 0..15 holds one neighbor index (int32)
        int myIdx = -1;
        if (lane < NK) myIdx = nbr[(size_t)n * NK + lane];
        unsigned vmask = __ballot_sync(0xFFFFFFFFu, (lane < NK) && (myIdx >= 0));
        int nvalid = __popc(vmask);

        // Own prob pair
        float p0 = 0.0f, p1 = 0.0f;
        if (active) {
            float2 pp = *reinterpret_cast<const float2*>(
                g_probs + (size_t)n * NCLS + 2 * pair);
            p0 = pp.x; p1 = pp.y;
        }

        float acc = 0.0f;
        if (pvalid && nvalid > 0) {
#pragma unroll
            for (int s = 0; s < 8; s++) {
                int src = 2 * s + grp;
                int q = __shfl_sync(0xFFFFFFFFu, myIdx, src);
                if (active && q >= 0) {
                    float2 qq = *reinterpret_cast<const float2*>(
                        g_probs + (size_t)q * NCLS + 2 * pair);
                    float d0 = p0 - qq.x;
                    float d1 = p1 - qq.y;
                    acc = fmaf(d0, d0, acc);
                    acc = fmaf(d1, d1, acc);
                }
            }
        }

        // Warp butterfly reduce (inactive lanes carry 0)
#pragma unroll
        for (int o = 16; o > 0; o >>= 1)
            acc += __shfl_xor_sync(0xFFFFFFFFu, acc, o);

        if (lane == 0 && pvalid) {
            float denom = (float)(nvalid > 0 ? nvalid : 1);
            warpSum += acc / denom;
            warpCnt += 1.0f;
        }
    }

    // Block reduce, one atomic pair per block
    __shared__ float sSum[32];
    __shared__ float sCnt[32];
    if (lane == 0) { sSum[warpInBlock] = warpSum; sCnt[warpInBlock] = warpCnt; }
    __syncthreads();
    if (threadIdx.x == 0) {
        float bs = 0.0f, bc = 0.0f;
        for (int w = 0; w < warpsPerBlock; w++) { bs += sSum[w]; bc += sCnt[w]; }
        atomicAdd(&g_acc[0], bs);
        atomicAdd(&g_acc[1], bc);
    }
}

__global__ void finalize_kernel(float* __restrict__ out) {
    out[0] = (g_acc[0] / fmaxf(g_acc[1], 1.0f)) * 1.0f /* LOSS_WEIGHT */;
}

extern "C" void kernel_launch(void* const* d_in, const int* in_sizes, int n_in,
                              void* d_out, int out_size) {
    // Identify inputs by element count (robust to metadata ordering):
    //   seg_logits: 500000*20 = 10,000,000 (float32)
    //   neighbor_index: 500000*16 = 8,000,000 (int32 — JAX x64 disabled)
    //   labels: 500,000 (int32)
    const float* logits = nullptr;
    const int*   nbr    = nullptr;
    const int*   labels = nullptr;
    for (int i = 0; i < n_in; i++) {
        if (in_sizes[i] == NPTS * NCLS)      logits = (const float*)d_in[i];
        else if (in_sizes[i] == NPTS * NK)   nbr    = (const int*)d_in[i];
        else if (in_sizes[i] == NPTS)        labels = (const int*)d_in[i];
    }
    float* out = (float*)d_out;

    zero_acc_kernel<<<1, 1>>>();
    softmax_kernel<<<(NPTS + 255) / 256, 256>>>(logits);
    loss_kernel<<<2048, 256>>>(nbr, labels);
    finalize_kernel<<<1, 1>>>(out);
}

// round 3
// speedup vs baseline: 1.0857x; 1.0857x over previous
#include <cuda_runtime.h>
#include <cuda_fp16.h>

#define NPTS 500000
#define NCLS 20
#define NK   16

// fp16 probs table: 500000*20*2B = 20 MB (L2-resident). Device globals (no alloc).
__device__ __half g_probs_h[(size_t)NPTS * NCLS];
__device__ float  g_acc[2];    // [0]=sum of mean_dist over valid pts, [1]=valid count
__device__ int    g_done = 0;  // loss-kernel block completion counter

// Kernel 1: softmax (fp32 in, fp16 out) + accumulator reset.
__global__ void softmax_kernel(const float* __restrict__ logits) {
    if (blockIdx.x == 0 && threadIdx.x == 0) {
        g_acc[0] = 0.0f;
        g_acc[1] = 0.0f;
        g_done   = 0;
    }
    int n = blockIdx.x * blockDim.x + threadIdx.x;
    if (n >= NPTS) return;
    const float4* src = reinterpret_cast<const float4*>(logits + (size_t)n * NCLS);
    float4 v[5];
#pragma unroll
    for (int i = 0; i < 5; i++) v[i] = src[i];
    float* f = reinterpret_cast<float*>(v);
    float m = f[0];
#pragma unroll
    for (int i = 1; i < NCLS; i++) m = fmaxf(m, f[i]);
    float s = 0.0f;
#pragma unroll
    for (int i = 0; i < NCLS; i++) { f[i] = __expf(f[i] - m); s += f[i]; }
    float inv = 1.0f / s;
    // Pack to half2 pairs; row base = n*40 B (8-byte aligned) -> uint2-safe stores
    __half2* dst = reinterpret_cast<__half2*>(g_probs_h + (size_t)n * NCLS);
#pragma unroll
    for (int i = 0; i < 10; i++)
        dst[i] = __floats2half2_rn(f[2 * i] * inv, f[2 * i + 1] * inv);
}

// Kernel 2: warp-per-point gather + distance + global reduce + finalize.
// Lane layout: grp = lane>>3 (0..3), sub = lane&7; active lanes sub<5 own
// classes [4*sub, 4*sub+4) as uint2 (two half2). Step s (0..3): group g
// processes neighbor 4*s+g -> one LDG.64 instruction covers 4 neighbor rows.
__global__ void loss_kernel(const int* __restrict__ nbr,
                            const int* __restrict__ labels,
                            float* __restrict__ out) {
    const int lane = threadIdx.x & 31;
    const int warpInBlock = threadIdx.x >> 5;
    const int warpsPerBlock = blockDim.x >> 5;
    const int gwarp = blockIdx.x * warpsPerBlock + warpInBlock;
    const int totalWarps = gridDim.x * warpsPerBlock;
    const int grp = lane >> 3;
    const int sub = lane & 7;
    const bool active = (sub < 5);

    float warpSum = 0.0f;
    float warpCnt = 0.0f;

    for (int n = gwarp; n < NPTS; n += totalWarps) {
        int lab = labels[n];                    // same addr all lanes -> broadcast
        bool pvalid = (lab != -1);

        int myIdx = -1;
        if (lane < NK) myIdx = nbr[(size_t)n * NK + lane];
        unsigned vmask = __ballot_sync(0xFFFFFFFFu, (lane < NK) && (myIdx >= 0));
        int nvalid = __popc(vmask);

        // Own 4 classes in fp32
        float p0 = 0.f, p1 = 0.f, p2 = 0.f, p3 = 0.f;
        if (active) {
            uint2 pw = *reinterpret_cast<const uint2*>(
                g_probs_h + (size_t)n * NCLS + 4 * sub);
            float2 a = __half22float2(*reinterpret_cast<__half2*>(&pw.x));
            float2 b = __half22float2(*reinterpret_cast<__half2*>(&pw.y));
            p0 = a.x; p1 = a.y; p2 = b.x; p3 = b.y;
        }

        float acc = 0.0f;
        if (pvalid && nvalid > 0) {
#pragma unroll
            for (int s = 0; s < 4; s++) {
                int q = __shfl_sync(0xFFFFFFFFu, myIdx, 4 * s + grp);
                if (active && q >= 0) {
                    uint2 qw = *reinterpret_cast<const uint2*>(
                        g_probs_h + (size_t)q * NCLS + 4 * sub);
                    float2 a = __half22float2(*reinterpret_cast<__half2*>(&qw.x));
                    float2 b = __half22float2(*reinterpret_cast<__half2*>(&qw.y));
                    float d0 = p0 - a.x, d1 = p1 - a.y;
                    float d2 = p2 - b.x, d3 = p3 - b.y;
                    acc = fmaf(d0, d0, acc);
                    acc = fmaf(d1, d1, acc);
                    acc = fmaf(d2, d2, acc);
                    acc = fmaf(d3, d3, acc);
                }
            }
        }

        // Butterfly reduce over all 32 lanes (covers classes x neighbors)
#pragma unroll
        for (int o = 16; o > 0; o >>= 1)
            acc += __shfl_xor_sync(0xFFFFFFFFu, acc, o);

        if (lane == 0 && pvalid) {
            warpSum += acc / (float)(nvalid > 0 ? nvalid : 1);
            warpCnt += 1.0f;
        }
    }

    // Block reduce -> one atomic pair per block
    __shared__ float sSum[32];
    __shared__ float sCnt[32];
    if (lane == 0) { sSum[warpInBlock] = warpSum; sCnt[warpInBlock] = warpCnt; }
    __syncthreads();
    if (threadIdx.x == 0) {
        float bs = 0.0f, bc = 0.0f;
        for (int w = 0; w < warpsPerBlock; w++) { bs += sSum[w]; bc += sCnt[w]; }
        atomicAdd(&g_acc[0], bs);
        atomicAdd(&g_acc[1], bc);
        __threadfence();
        int t = atomicAdd(&g_done, 1);
        if (t == gridDim.x - 1) {
            // Last block: all atomics visible. Finalize + reset counter.
            out[0] = g_acc[0] / fmaxf(g_acc[1], 1.0f);  // LOSS_WEIGHT = 1.0
            g_done = 0;
        }
    }
}

extern "C" void kernel_launch(void* const* d_in, const int* in_sizes, int n_in,
                              void* d_out, int out_size) {
    // Identify inputs by element count (robust to metadata ordering):
    //   seg_logits: 10,000,000 f32 / neighbor_index: 8,000,000 i32 / labels: 500,000 i32
    const float* logits = nullptr;
    const int*   nbr    = nullptr;
    const int*   labels = nullptr;
    for (int i = 0; i < n_in; i++) {
        if (in_sizes[i] == NPTS * NCLS)    logits = (const float*)d_in[i];
        else if (in_sizes[i] == NPTS * NK) nbr    = (const int*)d_in[i];
        else if (in_sizes[i] == NPTS)      labels = (const int*)d_in[i];
    }
    float* out = (float*)d_out;

    softmax_kernel<<<(NPTS + 255) / 256, 256>>>(logits);
    loss_kernel<<<2048, 256>>>(nbr, labels, out);
}

// round 4
// speedup vs baseline: 1.2423x; 1.1443x over previous
#include <cuda_runtime.h>
#include <cuda_fp16.h>

#define NPTS 500000
#define NCLS 20
#define NK   16

// fp16 probs table: 500000*20*2B = 20 MB (L2-resident). Device globals (no alloc).
__device__ __half g_probs_h[(size_t)NPTS * NCLS];
__device__ float  g_acc[2];    // [0]=sum of mean_dist over valid pts, [1]=valid count
__device__ int    g_done = 0;

// Kernel 1: softmax (fp32 in, fp16 out) + accumulator reset.
__global__ void softmax_kernel(const float* __restrict__ logits) {
    if (blockIdx.x == 0 && threadIdx.x == 0) {
        g_acc[0] = 0.0f;
        g_acc[1] = 0.0f;
        g_done   = 0;
    }
    int n = blockIdx.x * blockDim.x + threadIdx.x;
    if (n >= NPTS) return;
    const float4* src = reinterpret_cast<const float4*>(logits + (size_t)n * NCLS);
    float4 v[5];
#pragma unroll
    for (int i = 0; i < 5; i++) v[i] = src[i];
    float* f = reinterpret_cast<float*>(v);
    float m = f[0];
#pragma unroll
    for (int i = 1; i < NCLS; i++) m = fmaxf(m, f[i]);
    float s = 0.0f;
#pragma unroll
    for (int i = 0; i < NCLS; i++) { f[i] = __expf(f[i] - m); s += f[i]; }
    float inv = 1.0f / s;
    __half2* dst = reinterpret_cast<__half2*>(g_probs_h + (size_t)n * NCLS);
#pragma unroll
    for (int i = 0; i < 10; i++)
        dst[i] = __floats2half2_rn(f[2 * i] * inv, f[2 * i + 1] * inv);
}

// Kernel 2: warp-per-point gather; half2 math; per-lane scaled accumulation
// (one butterfly reduce per warp-loop, not per point).
// Lane layout: grp = lane>>3 (0..3), sub = lane&7; lanes with sub<5 own classes
// [4*sub,4*sub+4) as uint2 (two half2). Step s (0..3): group g handles neighbor
// 4*s+g -> one LDG.64 instruction gathers 4 neighbor rows.
__global__ void loss_kernel(const int* __restrict__ nbr,
                            const int* __restrict__ labels,
                            float* __restrict__ out) {
    const int lane = threadIdx.x & 31;
    const int warpInBlock = threadIdx.x >> 5;
    const int warpsPerBlock = blockDim.x >> 5;
    const int gwarp = blockIdx.x * warpsPerBlock + warpInBlock;
    const int totalWarps = gridDim.x * warpsPerBlock;
    const int grp = lane >> 3;
    const int sub = lane & 7;
    const bool active = (sub < 5);
    const int laneOff = 4 * sub;          // half offset within a row

    float accTot = 0.0f;   // per-lane: sum over points of acc_pt / nvalid
    float cnt    = 0.0f;   // valid-point count (identical on all lanes)

    for (int n = gwarp; n < NPTS; n += totalWarps) {
        const int rowOff = n * NCLS;       // fits int32 (max 1e7)
        int lab = labels[n];
        bool pvalid = (lab != -1);

        int myIdx = -1;
        if (lane < NK) myIdx = nbr[n * NK + lane];
        unsigned vmask = __ballot_sync(0xFFFFFFFFu, (lane < NK) && (myIdx >= 0));
        int nvalid = __popc(vmask);

        // Own 4 classes as two half2
        __half2 pa = __float2half2_rn(0.f), pb = pa;
        if (active) {
            uint2 pw = *reinterpret_cast<const uint2*>(g_probs_h + rowOff + laneOff);
            pa = *reinterpret_cast<__half2*>(&pw.x);
            pb = *reinterpret_cast<__half2*>(&pw.y);
        }

        __half2 acc2 = __float2half2_rn(0.f);
        if (pvalid && nvalid > 0) {
#pragma unroll
            for (int s = 0; s < 4; s++) {
                int q = __shfl_sync(0xFFFFFFFFu, myIdx, 4 * s + grp);
                if (active && q >= 0) {
                    uint2 qw = *reinterpret_cast<const uint2*>(
                        g_probs_h + q * NCLS + laneOff);
                    __half2 da = __hsub2(pa, *reinterpret_cast<__half2*>(&qw.x));
                    __half2 db = __hsub2(pb, *reinterpret_cast<__half2*>(&qw.y));
                    acc2 = __hfma2(da, da, acc2);
                    acc2 = __hfma2(db, db, acc2);
                }
            }
            // Scale this point's partial by 1/nvalid, accumulate per-lane in fp32.
            float invv = __frcp_rn((float)nvalid);
            float2 af = __half22float2(acc2);
            accTot = fmaf(af.x + af.y, invv, accTot);
            cnt += 1.0f;
        } else if (pvalid) {
            cnt += 1.0f;   // valid point, zero valid neighbors: mean_dist = 0
        }
    }

    // One butterfly reduce per warp (covers class lanes x neighbor groups)
#pragma unroll
    for (int o = 16; o > 0; o >>= 1)
        accTot += __shfl_xor_sync(0xFFFFFFFFu, accTot, o);

    // Block reduce -> one atomic pair per block
    __shared__ float sSum[32];
    __shared__ float sCnt[32];
    if (lane == 0) { sSum[warpInBlock] = accTot; sCnt[warpInBlock] = cnt; }
    __syncthreads();
    if (threadIdx.x == 0) {
        float bs = 0.0f, bc = 0.0f;
        for (int w = 0; w < warpsPerBlock; w++) { bs += sSum[w]; bc += sCnt[w]; }
        atomicAdd(&g_acc[0], bs);
        atomicAdd(&g_acc[1], bc);
        __threadfence();
        int t = atomicAdd(&g_done, 1);
        if (t == gridDim.x - 1) {
            out[0] = g_acc[0] / fmaxf(g_acc[1], 1.0f);  // LOSS_WEIGHT = 1.0
            g_done = 0;
        }
    }
}

extern "C" void kernel_launch(void* const* d_in, const int* in_sizes, int n_in,
                              void* d_out, int out_size) {
    const float* logits = nullptr;
    const int*   nbr    = nullptr;
    const int*   labels = nullptr;
    for (int i = 0; i < n_in; i++) {
        if (in_sizes[i] == NPTS * NCLS)    logits = (const float*)d_in[i];
        else if (in_sizes[i] == NPTS * NK) nbr    = (const int*)d_in[i];
        else if (in_sizes[i] == NPTS)      labels = (const int*)d_in[i];
    }
    float* out = (float*)d_out;

    softmax_kernel<<<(NPTS + 255) / 256, 256>>>(logits);
    loss_kernel<<<2048, 256>>>(nbr, labels, out);
}

// round 5
// speedup vs baseline: 1.4368x; 1.1566x over previous
#include <cuda_runtime.h>
#include <cuda_fp16.h>

#define NPTS 500000
#define NCLS 20
#define NK   16

// fp16 probs table: 500000*20*2B = 20 MB (L2-resident). Device globals (no alloc).
__device__ __half g_probs_h[(size_t)NPTS * NCLS];
__device__ float  g_acc[2];    // [0]=sum of mean_dist over valid pts, [1]=valid count
__device__ int    g_done = 0;

// Kernel 1: softmax (fp32 in, fp16 out) + accumulator reset.
__global__ void softmax_kernel(const float* __restrict__ logits) {
    if (blockIdx.x == 0 && threadIdx.x == 0) {
        g_acc[0] = 0.0f;
        g_acc[1] = 0.0f;
        g_done   = 0;
    }
    int n = blockIdx.x * blockDim.x + threadIdx.x;
    if (n >= NPTS) return;
    const float4* src = reinterpret_cast<const float4*>(logits + (size_t)n * NCLS);
    float4 v[5];
#pragma unroll
    for (int i = 0; i < 5; i++) v[i] = src[i];
    float* f = reinterpret_cast<float*>(v);
    float m = f[0];
#pragma unroll
    for (int i = 1; i < NCLS; i++) m = fmaxf(m, f[i]);
    float s = 0.0f;
#pragma unroll
    for (int i = 0; i < NCLS; i++) { f[i] = __expf(f[i] - m); s += f[i]; }
    float inv = 1.0f / s;
    __half2* dst = reinterpret_cast<__half2*>(g_probs_h + (size_t)n * NCLS);
#pragma unroll
    for (int i = 0; i < 10; i++)
        dst[i] = __floats2half2_rn(f[2 * i] * inv, f[2 * i + 1] * inv);
}

// Kernel 2: warp-per-point gather, 2 points in flight per iteration (MLP x2).
// Lane layout: grp = lane>>3 (0..3), sub = lane&7; lanes with sub<5 own classes
// [4*sub,4*sub+4) as uint2 (two half2). Step s (0..3): group g handles neighbor
// 4*s+g -> one LDG.64 instruction gathers 4 neighbor rows.
__global__ void loss_kernel(const int* __restrict__ nbr,
                            const int* __restrict__ labels,
                            float* __restrict__ out) {
    const int lane = threadIdx.x & 31;
    const int warpInBlock = threadIdx.x >> 5;
    const int warpsPerBlock = blockDim.x >> 5;
    const int gwarp = blockIdx.x * warpsPerBlock + warpInBlock;
    const int totalWarps = gridDim.x * warpsPerBlock;
    const int grp = lane >> 3;
    const int sub = lane & 7;
    const bool active = (sub < 5);
    const int laneOff = 4 * sub;

    float accTot = 0.0f;
    float cnt    = 0.0f;

    const __half2 z2 = __float2half2_rn(0.f);

    for (int n = gwarp; n < NPTS; n += 2 * totalWarps) {
        const int n1 = n + totalWarps;
        const bool has1 = (n1 < NPTS);

        // ---- issue all front loads for BOTH points ----
        int lab0 = labels[n];
        int lab1 = has1 ? labels[n1] : -1;

        int idx0 = -1, idx1 = -1;
        if (lane < NK) {
            idx0 = nbr[n * NK + lane];
            if (has1) idx1 = nbr[n1 * NK + lane];
        }

        __half2 pa0 = z2, pb0 = z2, pa1 = z2, pb1 = z2;
        if (active) {
            uint2 pw0 = *reinterpret_cast<const uint2*>(g_probs_h + n * NCLS + laneOff);
            pa0 = *reinterpret_cast<__half2*>(&pw0.x);
            pb0 = *reinterpret_cast<__half2*>(&pw0.y);
            if (has1) {
                uint2 pw1 = *reinterpret_cast<const uint2*>(g_probs_h + n1 * NCLS + laneOff);
                pa1 = *reinterpret_cast<__half2*>(&pw1.x);
                pb1 = *reinterpret_cast<__half2*>(&pw1.y);
            }
        }

        unsigned vm0 = __ballot_sync(0xFFFFFFFFu, (lane < NK) && (idx0 >= 0));
        unsigned vm1 = __ballot_sync(0xFFFFFFFFu, (lane < NK) && (idx1 >= 0));
        int nv0 = __popc(vm0);
        int nv1 = __popc(vm1);
        bool pv0 = (lab0 != -1);
        bool pv1 = has1 && (lab1 != -1);

        // ---- all 8 shuffles, then all 8 gathers in flight ----
        int q0[4], q1[4];
#pragma unroll
        for (int s = 0; s < 4; s++) {
            q0[s] = __shfl_sync(0xFFFFFFFFu, idx0, 4 * s + grp);
            q1[s] = __shfl_sync(0xFFFFFFFFu, idx1, 4 * s + grp);
        }

        __half2 acc0 = z2, acc1 = z2;
        bool do0 = pv0 && nv0 > 0;
        bool do1 = pv1 && nv1 > 0;
#pragma unroll
        for (int s = 0; s < 4; s++) {
            if (do0 && active && q0[s] >= 0) {
                uint2 qw = *reinterpret_cast<const uint2*>(
                    g_probs_h + q0[s] * NCLS + laneOff);
                __half2 da = __hsub2(pa0, *reinterpret_cast<__half2*>(&qw.x));
                __half2 db = __hsub2(pb0, *reinterpret_cast<__half2*>(&qw.y));
                acc0 = __hfma2(da, da, acc0);
                acc0 = __hfma2(db, db, acc0);
            }
            if (do1 && active && q1[s] >= 0) {
                uint2 qw = *reinterpret_cast<const uint2*>(
                    g_probs_h + q1[s] * NCLS + laneOff);
                __half2 da = __hsub2(pa1, *reinterpret_cast<__half2*>(&qw.x));
                __half2 db = __hsub2(pb1, *reinterpret_cast<__half2*>(&qw.y));
                acc1 = __hfma2(da, da, acc1);
                acc1 = __hfma2(db, db, acc1);
            }
        }

        if (do0) {
            float2 af = __half22float2(acc0);
            accTot = fmaf(af.x + af.y, __frcp_rn((float)nv0), accTot);
        }
        if (do1) {
            float2 af = __half22float2(acc1);
            accTot = fmaf(af.x + af.y, __frcp_rn((float)nv1), accTot);
        }
        cnt += (pv0 ? 1.0f : 0.0f) + (pv1 ? 1.0f : 0.0f);
    }

    // One butterfly reduce per warp
#pragma unroll
    for (int o = 16; o > 0; o >>= 1)
        accTot += __shfl_xor_sync(0xFFFFFFFFu, accTot, o);

    // Block reduce -> one atomic pair per block
    __shared__ float sSum[32];
    __shared__ float sCnt[32];
    if (lane == 0) { sSum[warpInBlock] = accTot; sCnt[warpInBlock] = cnt; }
    __syncthreads();
    if (threadIdx.x == 0) {
        float bs = 0.0f, bc = 0.0f;
        for (int w = 0; w < warpsPerBlock; w++) { bs += sSum[w]; bc += sCnt[w]; }
        atomicAdd(&g_acc[0], bs);
        atomicAdd(&g_acc[1], bc);
        __threadfence();
        int t = atomicAdd(&g_done, 1);
        if (t == gridDim.x - 1) {
            out[0] = g_acc[0] / fmaxf(g_acc[1], 1.0f);  // LOSS_WEIGHT = 1.0
            g_done = 0;
        }
    }
}

extern "C" void kernel_launch(void* const* d_in, const int* in_sizes, int n_in,
                              void* d_out, int out_size) {
    const float* logits = nullptr;
    const int*   nbr    = nullptr;
    const int*   labels = nullptr;
    for (int i = 0; i < n_in; i++) {
        if (in_sizes[i] == NPTS * NCLS)    logits = (const float*)d_in[i];
        else if (in_sizes[i] == NPTS * NK) nbr    = (const int*)d_in[i];
        else if (in_sizes[i] == NPTS)      labels = (const int*)d_in[i];
    }
    float* out = (float*)d_out;

    softmax_kernel<<<(NPTS + 255) / 256, 256>>>(logits);
    loss_kernel<<<2048, 256>>>(nbr, labels, out);
}